// round 6
// baseline (speedup 1.0000x reference)
#include <cuda_runtime.h>
#include <cuda_bf16.h>

// Problem constants (B=4, N=512, D=128)
#define PB 4
#define PN 512
#define PD 128

// Scratch (allocation-free rule: __device__ globals)
__device__ float g_sq[PB * PN];
__device__ float g_sk[PB * PN];

// ---------------------------------------------------------------------------
// Kernel 1: fused LayerNorm + decomposed linear -> per-row scores sq, sk.
// One warp per (b,n) row. Each lane owns 4 consecutive channels (float4).
// ---------------------------------------------------------------------------
__global__ void scores_kernel(const float* __restrict__ emb,
                              const float* __restrict__ att_w,
                              const float* __restrict__ ln_g,
                              const float* __restrict__ ln_b) {
    int gw = (blockIdx.x * blockDim.x + threadIdx.x) >> 5;   // global warp = row id
    if (gw >= PB * PN) return;
    int lane = threadIdx.x & 31;

    float4 x = ((const float4*)emb)[gw * 32 + lane];

    // mean
    float s = x.x + x.y + x.z + x.w;
#pragma unroll
    for (int o = 16; o; o >>= 1) s += __shfl_xor_sync(0xffffffffu, s, o);
    float mu = s * (1.0f / PD);

    // variance
    float dx0 = x.x - mu, dx1 = x.y - mu, dx2 = x.z - mu, dx3 = x.w - mu;
    float v = dx0 * dx0 + dx1 * dx1 + dx2 * dx2 + dx3 * dx3;
#pragma unroll
    for (int o = 16; o; o >>= 1) v += __shfl_xor_sync(0xffffffffu, v, o);
    float rstd = rsqrtf(v * (1.0f / PD) + 1e-5f);

    float4 gg = ((const float4*)ln_g)[lane];
    float4 bb = ((const float4*)ln_b)[lane];
    float n0 = dx0 * rstd * gg.x + bb.x;
    float n1 = dx1 * rstd * gg.y + bb.y;
    float n2 = dx2 * rstd * gg.z + bb.z;
    float n3 = dx3 * rstd * gg.w + bb.w;

    float4 wq = ((const float4*)att_w)[lane];        // att_w[0, 0:128]
    float4 wk = ((const float4*)att_w)[32 + lane];   // att_w[0, 128:256]

    float q = n0 * wq.x + n1 * wq.y + n2 * wq.z + n3 * wq.w;
    float k = n0 * wk.x + n1 * wk.y + n2 * wk.z + n3 * wk.w;
#pragma unroll
    for (int o = 16; o; o >>= 1) {
        q += __shfl_xor_sync(0xffffffffu, q, o);
        k += __shfl_xor_sync(0xffffffffu, k, o);
    }
    if (lane == 0) {
        g_sq[gw] = q;
        g_sk[gw] = k;
    }
}

// ---------------------------------------------------------------------------
// Kernel 2 (fused): 2048 value tiles (TI=16 x TJ=32) + 2048 alphas rows.
// Value role: ei tile in smem (8x reuse); ej quads loaded DIRECTLY via LDG
// (zero cross-thread reuse -> smem staging was pure overhead). smem = 8 KB,
// __launch_bounds__(256,8) keeps regs <= 32 for full occupancy.
// ---------------------------------------------------------------------------
#define TI 16
#define TJ 32
#define NJT (PN / TJ)                    // 16 j-tiles
#define NIT (PN / TI)                    // 32 i-tiles
#define NVALBLK (PB * NIT * NJT)         // 2048
#define NALPHA  (PB * PN)                // 2048

__global__ __launch_bounds__(256, 8) void fused_kernel(const float* __restrict__ emb,
                                                       const float* __restrict__ att_b,
                                                       float* __restrict__ out_alphas,
                                                       float* __restrict__ out_val) {
    __shared__ float4 s_ei[TI * 32];     // 8 KB (value role) / 16 floats (alphas)

    int blk = blockIdx.x;
    int t   = threadIdx.x;

    if (blk < NVALBLK) {
        // ---------------- value role ----------------
        int jt = blk & 15;
        int it = (blk >> 4) & 31;
        int b  = blk >> 9;
        int i0 = it * TI;
        int j0 = jt * TJ;

        const float4* e = (const float4*)(emb) + (size_t)b * PN * 32;

        int d4 = t & 31;     // channel-quad index (0..31)
        int w8 = t >> 5;     // warp id (0..7) -> base jj

        // direct coalesced LDG of the 4 e_j quads this thread owns
        // (issued first to hide L2 latency behind the ei cooperative load)
        float4 bj0 = e[(size_t)(j0 + w8 +  0) * 32 + d4];
        float4 bj1 = e[(size_t)(j0 + w8 +  8) * 32 + d4];
        float4 bj2 = e[(size_t)(j0 + w8 + 16) * 32 + d4];
        float4 bj3 = e[(size_t)(j0 + w8 + 24) * 32 + d4];

        // cooperative ei tile load (32 float4 per row)
        for (int k = t; k < TI * 32; k += 256)
            s_ei[k] = e[(size_t)(i0 + (k >> 5)) * 32 + (k & 31)];
        __syncthreads();

        float4* outp = (float4*)out_val + ((size_t)(b * PN + i0) * PN + j0) * 32;

#pragma unroll
        for (int ii = 0; ii < TI; ii++) {
            float4 a = s_ei[ii * 32 + d4];
            float4* orow = outp + (size_t)ii * (PN * 32);

            float4 r;
            r.x = a.x * bj0.x; r.y = a.y * bj0.y; r.z = a.z * bj0.z; r.w = a.w * bj0.w;
            orow[(w8 +  0) * 32 + d4] = r;
            r.x = a.x * bj1.x; r.y = a.y * bj1.y; r.z = a.z * bj1.z; r.w = a.w * bj1.w;
            orow[(w8 +  8) * 32 + d4] = r;
            r.x = a.x * bj2.x; r.y = a.y * bj2.y; r.z = a.z * bj2.z; r.w = a.w * bj2.w;
            orow[(w8 + 16) * 32 + d4] = r;
            r.x = a.x * bj3.x; r.y = a.y * bj3.y; r.z = a.z * bj3.z; r.w = a.w * bj3.w;
            orow[(w8 + 24) * 32 + d4] = r;
        }
    } else {
        // ---------------- alphas role ----------------
        // alphas[b,i,:] = softmax_j( leaky( sq[b,i] + sk[b,j] + bias ) )
        float* red = (float*)s_ei;               // 16 floats of scratch

        int row = blk - NVALBLK;                 // b*N + i, 0..2047
        int b   = row >> 9;                      // N = 512
        int wid = t >> 5;                        // 0..7

        float sqi  = g_sq[row];
        float bias = att_b[0];

        float v[2];
        float m = -1e30f;
#pragma unroll
        for (int k = 0; k < 2; k++) {
            int j = t + (k << 8);
            float l = sqi + g_sk[(b << 9) + j] + bias;
            l = (l >= 0.0f) ? l : 0.01f * l;     // LeakyReLU(0.01)
            v[k] = l;
            m = fmaxf(m, l);
        }
        // block max (8 warps)
#pragma unroll
        for (int o = 16; o; o >>= 1) m = fmaxf(m, __shfl_xor_sync(0xffffffffu, m, o));
        if ((t & 31) == 0) red[wid] = m;
        __syncthreads();
        m = red[0];
#pragma unroll
        for (int w = 1; w < 8; w++) m = fmaxf(m, red[w]);
        __syncthreads();

        float s = 0.0f;
#pragma unroll
        for (int k = 0; k < 2; k++) {
            v[k] = __expf(v[k] - m);
            s += v[k];
        }
#pragma unroll
        for (int o = 16; o; o >>= 1) s += __shfl_xor_sync(0xffffffffu, s, o);
        if ((t & 31) == 0) red[8 + wid] = s;
        __syncthreads();
        s = red[8];
#pragma unroll
        for (int w = 1; w < 8; w++) s += red[8 + w];
        float inv = 1.0f / s;

        float* orow = out_alphas + (size_t)row * PN;
        orow[t]       = v[0] * inv;
        orow[t + 256] = v[1] * inv;
    }
}

// ---------------------------------------------------------------------------
// Launch. Output layout: [alphas (B*N*N floats), value (B*N*N*D floats)].
// ---------------------------------------------------------------------------
extern "C" void kernel_launch(void* const* d_in, const int* in_sizes, int n_in,
                              void* d_out, int out_size) {
    const float* emb   = (const float*)d_in[0];   // (B,N,D)
    const float* att_w = (const float*)d_in[1];   // (1,2D)
    const float* att_b = (const float*)d_in[2];   // (1,)
    const float* ln_g  = (const float*)d_in[3];   // (D,)
    const float* ln_b  = (const float*)d_in[4];   // (D,)

    float* out_alphas = (float*)d_out;
    float* out_value  = (float*)d_out + (size_t)PB * PN * PN;

    // 1) scores: 2048 rows, one warp each -> 256 blocks x 256 threads
    scores_kernel<<<(PB * PN) / 8, 256>>>(emb, att_w, ln_g, ln_b);

    // 2) fused: 2048 value blocks + 2048 alphas blocks at tail
    fused_kernel<<<NVALBLK + NALPHA, 256>>>(emb, att_b, out_alphas, out_value);
}

// round 7
// speedup vs baseline: 1.0457x; 1.0457x over previous
#include <cuda_runtime.h>
#include <cuda_bf16.h>

// Problem constants (B=4, N=512, D=128)
#define PB 4
#define PN 512
#define PD 128

// Scratch (allocation-free rule: __device__ globals)
__device__ float g_sq[PB * PN];
__device__ float g_sk[PB * PN];
__device__ int   g_flag = 0;   // scores-done block counter (self-resetting)
__device__ int   g_done = 0;   // alphas-done block counter (self-resetting)

// Grid layout: [scores 256 | value 2048 | alphas 2048]
#define TI 16
#define TJ 32
#define NSCORE  256                      // 8 warps/block, one warp per row
#define NVALBLK (PB * (PN / TI) * (PN / TJ))   // 2048
#define NALPHA  (PB * PN)                // 2048
#define VAL0    NSCORE
#define ALP0    (NSCORE + NVALBLK)

__global__ __launch_bounds__(256) void fused_all(const float* __restrict__ emb,
                                                 const float* __restrict__ att_w,
                                                 const float* __restrict__ att_b,
                                                 const float* __restrict__ ln_g,
                                                 const float* __restrict__ ln_b,
                                                 float* __restrict__ out_alphas,
                                                 float* __restrict__ out_val) {
    __shared__ float4 s_tiles[(TI + TJ) * 32];   // 24 KB value role; scratch otherwise

    int blk = blockIdx.x;
    int t   = threadIdx.x;

    if (blk < NSCORE) {
        // ================= scores role (wave-1 blocks) =================
        // One warp per (b,n) row: LayerNorm + decomposed linear -> sq, sk.
        int gw   = blk * 8 + (t >> 5);           // row id 0..2047
        int lane = t & 31;

        float4 x = ((const float4*)emb)[gw * 32 + lane];

        float s = x.x + x.y + x.z + x.w;
#pragma unroll
        for (int o = 16; o; o >>= 1) s += __shfl_xor_sync(0xffffffffu, s, o);
        float mu = s * (1.0f / PD);

        float dx0 = x.x - mu, dx1 = x.y - mu, dx2 = x.z - mu, dx3 = x.w - mu;
        float v = dx0 * dx0 + dx1 * dx1 + dx2 * dx2 + dx3 * dx3;
#pragma unroll
        for (int o = 16; o; o >>= 1) v += __shfl_xor_sync(0xffffffffu, v, o);
        float rstd = rsqrtf(v * (1.0f / PD) + 1e-5f);

        float4 gg = ((const float4*)ln_g)[lane];
        float4 bb = ((const float4*)ln_b)[lane];
        float n0 = dx0 * rstd * gg.x + bb.x;
        float n1 = dx1 * rstd * gg.y + bb.y;
        float n2 = dx2 * rstd * gg.z + bb.z;
        float n3 = dx3 * rstd * gg.w + bb.w;

        float4 wq = ((const float4*)att_w)[lane];        // att_w[0, 0:128]
        float4 wk = ((const float4*)att_w)[32 + lane];   // att_w[0, 128:256]

        float q = n0 * wq.x + n1 * wq.y + n2 * wq.z + n3 * wq.w;
        float k = n0 * wk.x + n1 * wk.y + n2 * wk.z + n3 * wk.w;
#pragma unroll
        for (int o = 16; o; o >>= 1) {
            q += __shfl_xor_sync(0xffffffffu, q, o);
            k += __shfl_xor_sync(0xffffffffu, k, o);
        }
        if (lane == 0) {
            g_sq[gw] = q;
            g_sk[gw] = k;
        }
        __syncthreads();
        if (t == 0) {
            __threadfence();                     // publish g_sq/g_sk
            atomicAdd(&g_flag, 1);
        }
    } else if (blk < ALP0) {
        // ================= value role (R5-exact) =================
        float4* ei = s_tiles;                    // TI rows x 32 quads
        float4* ej = s_tiles + TI * 32;          // TJ rows x 32 quads

        int vb = blk - VAL0;
        int jt = vb & 15;
        int it = (vb >> 4) & 31;
        int b  = vb >> 9;
        int i0 = it * TI;
        int j0 = jt * TJ;

        const float4* e = (const float4*)(emb) + (size_t)b * PN * 32;

        for (int k = t; k < TI * 32; k += 256)
            ei[k] = e[(size_t)(i0 + (k >> 5)) * 32 + (k & 31)];
        for (int k = t; k < TJ * 32; k += 256)
            ej[k] = e[(size_t)(j0 + (k >> 5)) * 32 + (k & 31)];
        __syncthreads();

        int d4 = t & 31;     // channel-quad index (0..31)
        int w8 = t >> 5;     // warp id (0..7) -> base jj

        float4 bj0 = ej[(w8 +  0) * 32 + d4];
        float4 bj1 = ej[(w8 +  8) * 32 + d4];
        float4 bj2 = ej[(w8 + 16) * 32 + d4];
        float4 bj3 = ej[(w8 + 24) * 32 + d4];

        float4* outp = (float4*)out_val + ((size_t)(b * PN + i0) * PN + j0) * 32;

#pragma unroll
        for (int ii = 0; ii < TI; ii++) {
            float4 a = ei[ii * 32 + d4];
            float4* orow = outp + (size_t)ii * (PN * 32);

            float4 r;
            r.x = a.x * bj0.x; r.y = a.y * bj0.y; r.z = a.z * bj0.z; r.w = a.w * bj0.w;
            __stcs(&orow[(w8 +  0) * 32 + d4], r);
            r.x = a.x * bj1.x; r.y = a.y * bj1.y; r.z = a.z * bj1.z; r.w = a.w * bj1.w;
            __stcs(&orow[(w8 +  8) * 32 + d4], r);
            r.x = a.x * bj2.x; r.y = a.y * bj2.y; r.z = a.z * bj2.z; r.w = a.w * bj2.w;
            __stcs(&orow[(w8 + 16) * 32 + d4], r);
            r.x = a.x * bj3.x; r.y = a.y * bj3.y; r.z = a.z * bj3.z; r.w = a.w * bj3.w;
            __stcs(&orow[(w8 + 24) * 32 + d4], r);
        }
    } else {
        // ================= alphas role (tail blocks) =================
        // alphas[b,i,:] = softmax_j( leaky( sq[b,i] + sk[b,j] + bias ) )
        float* red = (float*)s_tiles;            // 16 floats of scratch

        // acquire scores (flag was set ~wave 1; first poll passes in practice)
        if (t == 0) {
            while (atomicAdd(&g_flag, 0) < NSCORE) { }
            __threadfence();
        }
        __syncthreads();

        int row = blk - ALP0;                    // b*N + i, 0..2047
        int b   = row >> 9;                      // N = 512
        int wid = t >> 5;                        // 0..7

        float sqi  = g_sq[row];
        float bias = att_b[0];

        float v[2];
        float m = -1e30f;
#pragma unroll
        for (int k = 0; k < 2; k++) {
            int j = t + (k << 8);
            float l = sqi + g_sk[(b << 9) + j] + bias;
            l = (l >= 0.0f) ? l : 0.01f * l;     // LeakyReLU(0.01)
            v[k] = l;
            m = fmaxf(m, l);
        }
#pragma unroll
        for (int o = 16; o; o >>= 1) m = fmaxf(m, __shfl_xor_sync(0xffffffffu, m, o));
        if ((t & 31) == 0) red[wid] = m;
        __syncthreads();
        m = red[0];
#pragma unroll
        for (int w = 1; w < 8; w++) m = fmaxf(m, red[w]);
        __syncthreads();

        float s = 0.0f;
#pragma unroll
        for (int k = 0; k < 2; k++) {
            v[k] = __expf(v[k] - m);
            s += v[k];
        }
#pragma unroll
        for (int o = 16; o; o >>= 1) s += __shfl_xor_sync(0xffffffffu, s, o);
        if ((t & 31) == 0) red[8 + wid] = s;
        __syncthreads();
        s = red[8];
#pragma unroll
        for (int w = 1; w < 8; w++) s += red[8 + w];
        float inv = 1.0f / s;

        float* orow = out_alphas + (size_t)row * PN;
        __stcs(&orow[t],       v[0] * inv);
        __stcs(&orow[t + 256], v[1] * inv);

        // self-reset counters so every launch (and every graph replay) is identical
        __syncthreads();
        if (t == 0) {
            int v2 = atomicAdd(&g_done, 1);
            if (v2 == NALPHA - 1) {
                g_flag = 0;
                g_done = 0;
                __threadfence();
            }
        }
    }
}

// ---------------------------------------------------------------------------
// Launch. Output layout: [alphas (B*N*N floats), value (B*N*N*D floats)].
// ---------------------------------------------------------------------------
extern "C" void kernel_launch(void* const* d_in, const int* in_sizes, int n_in,
                              void* d_out, int out_size) {
    const float* emb   = (const float*)d_in[0];   // (B,N,D)
    const float* att_w = (const float*)d_in[1];   // (1,2D)
    const float* att_b = (const float*)d_in[2];   // (1,)
    const float* ln_g  = (const float*)d_in[3];   // (D,)
    const float* ln_b  = (const float*)d_in[4];   // (D,)

    float* out_alphas = (float*)d_out;
    float* out_value  = (float*)d_out + (size_t)PB * PN * PN;

    fused_all<<<NSCORE + NVALBLK + NALPHA, 256>>>(emb, att_w, att_b, ln_g, ln_b,
                                                  out_alphas, out_value);
}

// round 8
// speedup vs baseline: 1.0538x; 1.0078x over previous
#include <cuda_runtime.h>
#include <cuda_bf16.h>

// Problem constants (B=4, N=512, D=128)
#define PB 4
#define PN 512
#define PD 128

// Scratch (allocation-free rule: __device__ globals)
__device__ float g_sq[PB * PN];
__device__ float g_sk[PB * PN];
__device__ int   g_flag = 0;   // scores-done block counter (self-resetting)
__device__ int   g_done = 0;   // alphas-done block counter (self-resetting)

// Grid layout: [scores 256 | value 2048 | alphas 2048]
#define TI 16
#define TJ 32
#define NSCORE  256                      // 8 warps/block, one warp per row
#define NVALBLK (PB * (PN / TI) * (PN / TJ))   // 2048
#define NALPHA  (PB * PN)                // 2048
#define VAL0    NSCORE
#define ALP0    (NSCORE + NVALBLK)

__global__ __launch_bounds__(256, 6) void fused_all(const float* __restrict__ emb,
                                                    const float* __restrict__ att_w,
                                                    const float* __restrict__ att_b,
                                                    const float* __restrict__ ln_g,
                                                    const float* __restrict__ ln_b,
                                                    float* __restrict__ out_alphas,
                                                    float* __restrict__ out_val) {
    __shared__ float4 s_tiles[(TI + TJ) * 32];   // 24 KB value role; scratch otherwise

    int blk = blockIdx.x;
    int t   = threadIdx.x;

    if (blk < NSCORE) {
        // ================= scores role (wave-1 blocks) =================
        // One warp per (b,n) row: LayerNorm + decomposed linear -> sq, sk.
        int gw   = blk * 8 + (t >> 5);           // row id 0..2047
        int lane = t & 31;

        float4 x = ((const float4*)emb)[gw * 32 + lane];

        float s = x.x + x.y + x.z + x.w;
#pragma unroll
        for (int o = 16; o; o >>= 1) s += __shfl_xor_sync(0xffffffffu, s, o);
        float mu = s * (1.0f / PD);

        float dx0 = x.x - mu, dx1 = x.y - mu, dx2 = x.z - mu, dx3 = x.w - mu;
        float v = dx0 * dx0 + dx1 * dx1 + dx2 * dx2 + dx3 * dx3;
#pragma unroll
        for (int o = 16; o; o >>= 1) v += __shfl_xor_sync(0xffffffffu, v, o);
        float rstd = rsqrtf(v * (1.0f / PD) + 1e-5f);

        float4 gg = ((const float4*)ln_g)[lane];
        float4 bb = ((const float4*)ln_b)[lane];
        float n0 = dx0 * rstd * gg.x + bb.x;
        float n1 = dx1 * rstd * gg.y + bb.y;
        float n2 = dx2 * rstd * gg.z + bb.z;
        float n3 = dx3 * rstd * gg.w + bb.w;

        float4 wq = ((const float4*)att_w)[lane];        // att_w[0, 0:128]
        float4 wk = ((const float4*)att_w)[32 + lane];   // att_w[0, 128:256]

        float q = n0 * wq.x + n1 * wq.y + n2 * wq.z + n3 * wq.w;
        float k = n0 * wk.x + n1 * wk.y + n2 * wk.z + n3 * wk.w;
#pragma unroll
        for (int o = 16; o; o >>= 1) {
            q += __shfl_xor_sync(0xffffffffu, q, o);
            k += __shfl_xor_sync(0xffffffffu, k, o);
        }
        if (lane == 0) {
            g_sq[gw] = q;
            g_sk[gw] = k;
        }
        __syncthreads();
        if (t == 0) {
            __threadfence();                     // publish g_sq/g_sk
            atomicAdd(&g_flag, 1);
        }
    } else if (blk < ALP0) {
        // ================= value role (R5-exact) =================
        float4* ei = s_tiles;                    // TI rows x 32 quads
        float4* ej = s_tiles + TI * 32;          // TJ rows x 32 quads

        int vb = blk - VAL0;
        int jt = vb & 15;
        int it = (vb >> 4) & 31;
        int b  = vb >> 9;
        int i0 = it * TI;
        int j0 = jt * TJ;

        const float4* e = (const float4*)(emb) + (size_t)b * PN * 32;

        for (int k = t; k < TI * 32; k += 256)
            ei[k] = e[(size_t)(i0 + (k >> 5)) * 32 + (k & 31)];
        for (int k = t; k < TJ * 32; k += 256)
            ej[k] = e[(size_t)(j0 + (k >> 5)) * 32 + (k & 31)];
        __syncthreads();

        int d4 = t & 31;     // channel-quad index (0..31)
        int w8 = t >> 5;     // warp id (0..7) -> base jj

        float4 bj0 = ej[(w8 +  0) * 32 + d4];
        float4 bj1 = ej[(w8 +  8) * 32 + d4];
        float4 bj2 = ej[(w8 + 16) * 32 + d4];
        float4 bj3 = ej[(w8 + 24) * 32 + d4];

        float4* outp = (float4*)out_val + ((size_t)(b * PN + i0) * PN + j0) * 32;

#pragma unroll
        for (int ii = 0; ii < TI; ii++) {
            float4 a = ei[ii * 32 + d4];
            float4* orow = outp + (size_t)ii * (PN * 32);

            float4 r;
            r.x = a.x * bj0.x; r.y = a.y * bj0.y; r.z = a.z * bj0.z; r.w = a.w * bj0.w;
            __stcs(&orow[(w8 +  0) * 32 + d4], r);
            r.x = a.x * bj1.x; r.y = a.y * bj1.y; r.z = a.z * bj1.z; r.w = a.w * bj1.w;
            __stcs(&orow[(w8 +  8) * 32 + d4], r);
            r.x = a.x * bj2.x; r.y = a.y * bj2.y; r.z = a.z * bj2.z; r.w = a.w * bj2.w;
            __stcs(&orow[(w8 + 16) * 32 + d4], r);
            r.x = a.x * bj3.x; r.y = a.y * bj3.y; r.z = a.z * bj3.z; r.w = a.w * bj3.w;
            __stcs(&orow[(w8 + 24) * 32 + d4], r);
        }
    } else {
        // ================= alphas role (tail blocks) =================
        // alphas[b,i,:] = softmax_j( leaky( sq[b,i] + sk[b,j] + bias ) )
        float* red = (float*)s_tiles;            // 16 floats of scratch

        // acquire scores (flag was set ~wave 1; first poll passes in practice)
        if (t == 0) {
            while (atomicAdd(&g_flag, 0) < NSCORE) { }
            __threadfence();
        }
        __syncthreads();

        int row = blk - ALP0;                    // b*N + i, 0..2047
        int b   = row >> 9;                      // N = 512
        int wid = t >> 5;                        // 0..7

        float sqi  = g_sq[row];
        float bias = att_b[0];

        float v[2];
        float m = -1e30f;
#pragma unroll
        for (int k = 0; k < 2; k++) {
            int j = t + (k << 8);
            float l = sqi + g_sk[(b << 9) + j] + bias;
            l = (l >= 0.0f) ? l : 0.01f * l;     // LeakyReLU(0.01)
            v[k] = l;
            m = fmaxf(m, l);
        }
#pragma unroll
        for (int o = 16; o; o >>= 1) m = fmaxf(m, __shfl_xor_sync(0xffffffffu, m, o));
        if ((t & 31) == 0) red[wid] = m;
        __syncthreads();
        m = red[0];
#pragma unroll
        for (int w = 1; w < 8; w++) m = fmaxf(m, red[w]);
        __syncthreads();

        float s = 0.0f;
#pragma unroll
        for (int k = 0; k < 2; k++) {
            v[k] = __expf(v[k] - m);
            s += v[k];
        }
#pragma unroll
        for (int o = 16; o; o >>= 1) s += __shfl_xor_sync(0xffffffffu, s, o);
        if ((t & 31) == 0) red[8 + wid] = s;
        __syncthreads();
        s = red[8];
#pragma unroll
        for (int w = 1; w < 8; w++) s += red[8 + w];
        float inv = 1.0f / s;

        float* orow = out_alphas + (size_t)row * PN;
        __stcs(&orow[t],       v[0] * inv);
        __stcs(&orow[t + 256], v[1] * inv);

        // self-reset counters so every launch (and every graph replay) is identical
        __syncthreads();
        if (t == 0) {
            int v2 = atomicAdd(&g_done, 1);
            if (v2 == NALPHA - 1) {
                g_flag = 0;
                g_done = 0;
                __threadfence();
            }
        }
    }
}

// ---------------------------------------------------------------------------
// Launch. Output layout: [alphas (B*N*N floats), value (B*N*N*D floats)].
// ---------------------------------------------------------------------------
extern "C" void kernel_launch(void* const* d_in, const int* in_sizes, int n_in,
                              void* d_out, int out_size) {
    const float* emb   = (const float*)d_in[0];   // (B,N,D)
    const float* att_w = (const float*)d_in[1];   // (1,2D)
    const float* att_b = (const float*)d_in[2];   // (1,)
    const float* ln_g  = (const float*)d_in[3];   // (D,)
    const float* ln_b  = (const float*)d_in[4];   // (D,)

    float* out_alphas = (float*)d_out;
    float* out_value  = (float*)d_out + (size_t)PB * PN * PN;

    fused_all<<<NSCORE + NVALBLK + NALPHA, 256>>>(emb, att_w, att_b, ln_g, ln_b,
                                                  out_alphas, out_value);
}